// round 7
// baseline (speedup 1.0000x reference)
#include <cuda_runtime.h>

// TSControllerCoordinateTransform: x [1,10,T] f32, reference_axis [3] f32
// -> out [2,3,T] f32 (rows 0..2 = basis @ (Xpos - refPos), rows 3..5 = x rows 7..9)

#define T_LEN 4000000
#define T4 (T_LEN / 4)

// 9 reduction accumulators: S0,S1,S2 (sums), S00,S01,S02,S11,S12,S22 (product sums)
__device__ double g_sums[9];
// 12 transform params: basis row-major b[0..8], offsets o[0..2] (o_i = B_i . refPos)
__device__ float g_params[12];

// ---------------------------------------------------------------------------
// Kernel 0: zero accumulators
// ---------------------------------------------------------------------------
__global__ void k_zero() {
    if (threadIdx.x < 9) g_sums[threadIdx.x] = 0.0;
}

// ---------------------------------------------------------------------------
// Kernel 1: covariance reduction over rows 0..2 of x (float4 vectorized)
// ---------------------------------------------------------------------------
__global__ void k_reduce(const float4* __restrict__ x) {
    const float4* __restrict__ X0 = x;
    const float4* __restrict__ X1 = x + T4;
    const float4* __restrict__ X2 = x + 2 * T4;

    float s[9];
#pragma unroll
    for (int j = 0; j < 9; j++) s[j] = 0.0f;

    const int stride = gridDim.x * blockDim.x;
    for (int i = blockIdx.x * blockDim.x + threadIdx.x; i < T4; i += stride) {
        float4 a = X0[i];
        float4 b = X1[i];
        float4 c = X2[i];

        s[0] += (a.x + a.y) + (a.z + a.w);
        s[1] += (b.x + b.y) + (b.z + b.w);
        s[2] += (c.x + c.y) + (c.z + c.w);
        s[3] += (a.x * a.x + a.y * a.y) + (a.z * a.z + a.w * a.w);
        s[4] += (a.x * b.x + a.y * b.y) + (a.z * b.z + a.w * b.w);
        s[5] += (a.x * c.x + a.y * c.y) + (a.z * c.z + a.w * c.w);
        s[6] += (b.x * b.x + b.y * b.y) + (b.z * b.z + b.w * b.w);
        s[7] += (b.x * c.x + b.y * c.y) + (b.z * c.z + b.w * c.w);
        s[8] += (c.x * c.x + c.y * c.y) + (c.z * c.z + c.w * c.w);
    }

    // Warp shuffle reduce (f32 — partial magnitudes are tiny, error negligible)
#pragma unroll
    for (int off = 16; off > 0; off >>= 1) {
#pragma unroll
        for (int j = 0; j < 9; j++)
            s[j] += __shfl_down_sync(0xFFFFFFFFu, s[j], off);
    }

    __shared__ float sm[8][9];  // 256 threads = 8 warps
    const int wid = threadIdx.x >> 5;
    const int lid = threadIdx.x & 31;
    if (lid == 0) {
#pragma unroll
        for (int j = 0; j < 9; j++) sm[wid][j] = s[j];
    }
    __syncthreads();

    if (threadIdx.x < 9) {
        double t = 0.0;
#pragma unroll
        for (int w = 0; w < 8; w++) t += (double)sm[w][threadIdx.x];
        atomicAdd(&g_sums[threadIdx.x], t);
    }
}

// ---------------------------------------------------------------------------
// Kernel 2: finalize — build cov, fp64 Jacobi eigh, quaternion sign fix,
// cross-product basis, store 12 float params. Single thread.
// ---------------------------------------------------------------------------
__global__ void k_finalize(const float* __restrict__ x,
                           const float* __restrict__ ref_axis) {
    if (threadIdx.x != 0 || blockIdx.x != 0) return;

    const double T = (double)T_LEN;
    double S0 = g_sums[0], S1 = g_sums[1], S2 = g_sums[2];
    double S00 = g_sums[3], S01 = g_sums[4], S02 = g_sums[5];
    double S11 = g_sums[6], S12 = g_sums[7], S22 = g_sums[8];

    const double inv = 1.0 / (T - 1.0);
    double A[3][3];
    A[0][0] = (S00 - S0 * S0 / T) * inv;
    A[0][1] = A[1][0] = (S01 - S0 * S1 / T) * inv;
    A[0][2] = A[2][0] = (S02 - S0 * S2 / T) * inv;
    A[1][1] = (S11 - S1 * S1 / T) * inv;
    A[1][2] = A[2][1] = (S12 - S1 * S2 / T) * inv;
    A[2][2] = (S22 - S2 * S2 / T) * inv;

    double V[3][3] = {{1, 0, 0}, {0, 1, 0}, {0, 0, 1}};

    // Cyclic Jacobi sweeps (3x3 symmetric, fp64)
    for (int sweep = 0; sweep < 30; sweep++) {
        double off = fabs(A[0][1]) + fabs(A[0][2]) + fabs(A[1][2]);
        if (off < 1e-30) break;
        for (int pq = 0; pq < 3; pq++) {
            const int p = (pq == 2) ? 1 : 0;
            const int q = (pq == 0) ? 1 : 2;
            double apq = A[p][q];
            if (fabs(apq) < 1e-300) continue;
            double theta = (A[q][q] - A[p][p]) / (2.0 * apq);
            double t = ((theta >= 0.0) ? 1.0 : -1.0) /
                       (fabs(theta) + sqrt(theta * theta + 1.0));
            double c = 1.0 / sqrt(t * t + 1.0);
            double sgn = t * c;
            // A <- J^T A J  (columns p,q)
            for (int k = 0; k < 3; k++) {
                double akp = A[k][p], akq = A[k][q];
                A[k][p] = c * akp - sgn * akq;
                A[k][q] = sgn * akp + c * akq;
            }
            for (int k = 0; k < 3; k++) {
                double apk = A[p][k], aqk = A[q][k];
                A[p][k] = c * apk - sgn * aqk;
                A[q][k] = sgn * apk + c * aqk;
            }
            // V <- V J
            for (int k = 0; k < 3; k++) {
                double vkp = V[k][p], vkq = V[k][q];
                V[k][p] = c * vkp - sgn * vkq;
                V[k][q] = sgn * vkp + c * vkq;
            }
        }
    }

    // Top eigenvector (largest eigenvalue)
    int mi = 0;
    if (A[1][1] > A[mi][mi]) mi = 1;
    if (A[2][2] > A[mi][mi]) mi = 2;
    double z0 = V[0][mi], z1 = V[1][mi], z2 = V[2][mi];

    // Quaternion forward axis: rotate (0,0,1) by raw (unnormalized) Qrot,
    // replicating the reference formula exactly.
    double qx = (double)x[3 * T_LEN];
    double qy = (double)x[4 * T_LEN];
    double qz = (double)x[5 * T_LEN];
    double qw = (double)x[6 * T_LEN];
    double zf0 = 2.0 * (qx * qz + qw * qy);
    double zf1 = 2.0 * (qy * qz - qw * qx);
    double zf2 = 1.0 - 2.0 * (qx * qx + qy * qy);

    if (zf0 * z0 + zf1 * z1 + zf2 * z2 < 0.0) {
        z0 = -z0; z1 = -z1; z2 = -z2;
    }

    double u0 = (double)ref_axis[0], u1 = (double)ref_axis[1], u2 = (double)ref_axis[2];
    // new_right = cross(up, z)
    double r0 = u1 * z2 - u2 * z1;
    double r1 = u2 * z0 - u0 * z2;
    double r2 = u0 * z1 - u1 * z0;
    // new_fwd = cross(right, up)
    double f0 = r1 * u2 - r2 * u1;
    double f1 = r2 * u0 - r0 * u2;
    double f2 = r0 * u1 - r1 * u0;

    // refPos = Xpos[:, :, 0]
    double p0 = (double)x[0];
    double p1 = (double)x[T_LEN];
    double p2 = (double)x[2 * T_LEN];

    double B[3][3] = {{r0, r1, r2}, {u0, u1, u2}, {f0, f1, f2}};
    for (int i = 0; i < 3; i++) {
        g_params[3 * i + 0] = (float)B[i][0];
        g_params[3 * i + 1] = (float)B[i][1];
        g_params[3 * i + 2] = (float)B[i][2];
        g_params[9 + i] = (float)(B[i][0] * p0 + B[i][1] * p1 + B[i][2] * p2);
    }
}

// ---------------------------------------------------------------------------
// Kernel 3: streaming transform + copy (float4 vectorized)
// out rows 0..2 = B @ Xpos - o ; out rows 3..5 = x rows 7..9
// ---------------------------------------------------------------------------
__global__ void k_transform(const float4* __restrict__ x,
                            float4* __restrict__ out) {
    const int i = blockIdx.x * blockDim.x + threadIdx.x;
    if (i >= T4) return;

    const float b00 = g_params[0], b01 = g_params[1], b02 = g_params[2];
    const float b10 = g_params[3], b11 = g_params[4], b12 = g_params[5];
    const float b20 = g_params[6], b21 = g_params[7], b22 = g_params[8];
    const float o0 = g_params[9], o1 = g_params[10], o2 = g_params[11];

    float4 a = x[i];            // row 0 (likely L2-resident from reduce)
    float4 b = x[T4 + i];       // row 1
    float4 c = x[2 * T4 + i];   // row 2

    float4 y0, y1, y2;
    y0.x = fmaf(b00, a.x, fmaf(b01, b.x, fmaf(b02, c.x, -o0)));
    y0.y = fmaf(b00, a.y, fmaf(b01, b.y, fmaf(b02, c.y, -o0)));
    y0.z = fmaf(b00, a.z, fmaf(b01, b.z, fmaf(b02, c.z, -o0)));
    y0.w = fmaf(b00, a.w, fmaf(b01, b.w, fmaf(b02, c.w, -o0)));

    y1.x = fmaf(b10, a.x, fmaf(b11, b.x, fmaf(b12, c.x, -o1)));
    y1.y = fmaf(b10, a.y, fmaf(b11, b.y, fmaf(b12, c.y, -o1)));
    y1.z = fmaf(b10, a.z, fmaf(b11, b.z, fmaf(b12, c.z, -o1)));
    y1.w = fmaf(b10, a.w, fmaf(b11, b.w, fmaf(b12, c.w, -o1)));

    y2.x = fmaf(b20, a.x, fmaf(b21, b.x, fmaf(b22, c.x, -o2)));
    y2.y = fmaf(b20, a.y, fmaf(b21, b.y, fmaf(b22, c.y, -o2)));
    y2.z = fmaf(b20, a.z, fmaf(b21, b.z, fmaf(b22, c.z, -o2)));
    y2.w = fmaf(b20, a.w, fmaf(b21, b.w, fmaf(b22, c.w, -o2)));

    // Streaming stores: output is never re-read; keep L2 for Xpos.
    __stcs(&out[i], y0);
    __stcs(&out[T4 + i], y1);
    __stcs(&out[2 * T4 + i], y2);

    // Add rows 7..9: streamed read, streamed write.
    float4 a0 = __ldcs(&x[7 * T4 + i]);
    float4 a1 = __ldcs(&x[8 * T4 + i]);
    float4 a2 = __ldcs(&x[9 * T4 + i]);
    __stcs(&out[3 * T4 + i], a0);
    __stcs(&out[4 * T4 + i], a1);
    __stcs(&out[5 * T4 + i], a2);
}

// ---------------------------------------------------------------------------
extern "C" void kernel_launch(void* const* d_in, const int* in_sizes, int n_in,
                              void* d_out, int out_size) {
    const float* x = (const float*)d_in[0];
    const float* ref_axis = (const float*)d_in[1];
    float* out = (float*)d_out;

    k_zero<<<1, 32>>>();
    k_reduce<<<1184, 256>>>((const float4*)x);
    k_finalize<<<1, 1>>>(x, ref_axis);
    k_transform<<<(T4 + 255) / 256, 256>>>((const float4*)x, (float4*)out);
}

// round 9
// speedup vs baseline: 1.5207x; 1.5207x over previous
#include <cuda_runtime.h>
#include <math.h>

// TSControllerCoordinateTransform: x [1,10,T] f32, reference_axis [3] f32
// -> out [2,3,T] f32 (rows 0..2 = basis @ (Xpos - refPos), rows 3..5 = x rows 7..9)

#define T_LEN 4000000
#define T4 (T_LEN / 4)
#define NB_RED 1184   // reduce grid size (must match launch)

// Per-block partial sums: S0,S1,S2, S00,S01,S02,S11,S12,S22 (written fresh each call)
__device__ double g_part[NB_RED][9];
// 12 transform params: basis row-major b[0..8], offsets o[0..2] (o_i = B_i . refPos)
__device__ float g_params[12];

// ---------------------------------------------------------------------------
// Kernel 1: covariance partial reduction over rows 0..2 (float4 vectorized)
// Writes per-block partials — no zeroing, no atomics.
// ---------------------------------------------------------------------------
__global__ __launch_bounds__(256) void k_reduce(const float4* __restrict__ x) {
    const float4* __restrict__ X0 = x;
    const float4* __restrict__ X1 = x + T4;
    const float4* __restrict__ X2 = x + 2 * T4;

    float s[9];
#pragma unroll
    for (int j = 0; j < 9; j++) s[j] = 0.0f;

    const int stride = gridDim.x * blockDim.x;
    for (int i = blockIdx.x * blockDim.x + threadIdx.x; i < T4; i += stride) {
        float4 a = X0[i];
        float4 b = X1[i];
        float4 c = X2[i];

        s[0] += (a.x + a.y) + (a.z + a.w);
        s[1] += (b.x + b.y) + (b.z + b.w);
        s[2] += (c.x + c.y) + (c.z + c.w);
        s[3] += (a.x * a.x + a.y * a.y) + (a.z * a.z + a.w * a.w);
        s[4] += (a.x * b.x + a.y * b.y) + (a.z * b.z + a.w * b.w);
        s[5] += (a.x * c.x + a.y * c.y) + (a.z * c.z + a.w * c.w);
        s[6] += (b.x * b.x + b.y * b.y) + (b.z * b.z + b.w * b.w);
        s[7] += (b.x * c.x + b.y * c.y) + (b.z * c.z + b.w * c.w);
        s[8] += (c.x * c.x + c.y * c.y) + (c.z * c.z + c.w * c.w);
    }

#pragma unroll
    for (int off = 16; off > 0; off >>= 1) {
#pragma unroll
        for (int j = 0; j < 9; j++)
            s[j] += __shfl_down_sync(0xFFFFFFFFu, s[j], off);
    }

    __shared__ float sm[8][9];
    const int wid = threadIdx.x >> 5;
    const int lid = threadIdx.x & 31;
    if (lid == 0) {
#pragma unroll
        for (int j = 0; j < 9; j++) sm[wid][j] = s[j];
    }
    __syncthreads();

    if (threadIdx.x < 9) {
        double t = 0.0;
#pragma unroll
        for (int w = 0; w < 8; w++) t += (double)sm[w][threadIdx.x];
        g_part[blockIdx.x][threadIdx.x] = t;
    }
}

// ---------------------------------------------------------------------------
// Kernel 2: finalize — sum partials (9 warps), closed-form 3x3 eigh (fp64),
// quaternion sign fix, cross-product basis, store 12 float params.
// ---------------------------------------------------------------------------
__global__ void k_finalize(const float* __restrict__ x,
                           const float* __restrict__ ref_axis) {
    __shared__ double ssum[9];
    const int w = threadIdx.x >> 5;   // component index 0..8
    const int lane = threadIdx.x & 31;

    if (w < 9) {
        double t = 0.0;
        for (int i = lane; i < NB_RED; i += 32) t += g_part[i][w];
#pragma unroll
        for (int off = 16; off > 0; off >>= 1)
            t += __shfl_down_sync(0xFFFFFFFFu, t, off);
        if (lane == 0) ssum[w] = t;
    }
    __syncthreads();
    if (threadIdx.x != 0) return;

    const double T = (double)T_LEN;
    const double S0 = ssum[0], S1 = ssum[1], S2 = ssum[2];
    const double inv = 1.0 / (T - 1.0);
    const double a00 = (ssum[3] - S0 * S0 / T) * inv;
    const double a01 = (ssum[4] - S0 * S1 / T) * inv;
    const double a02 = (ssum[5] - S0 * S2 / T) * inv;
    const double a11 = (ssum[6] - S1 * S1 / T) * inv;
    const double a12 = (ssum[7] - S1 * S2 / T) * inv;
    const double a22 = (ssum[8] - S2 * S2 / T) * inv;

    // --- Closed-form largest eigenvalue (trigonometric method) ---
    const double m = (a00 + a11 + a22) * (1.0 / 3.0);
    const double d0 = a00 - m, d1 = a11 - m, d2 = a22 - m;
    const double p2 = d0 * d0 + d1 * d1 + d2 * d2 +
                      2.0 * (a01 * a01 + a02 * a02 + a12 * a12);
    double z0, z1, z2;
    if (p2 < 1e-300) {
        // cov ~ scalar * I: any unit vector is an eigenvector
        z0 = 0.0; z1 = 0.0; z2 = 1.0;
    } else {
        const double p = sqrt(p2 * (1.0 / 6.0));
        const double ip = 1.0 / p;
        // det((A - m I)/p) / 2
        const double b00 = d0 * ip, b11 = d1 * ip, b22 = d2 * ip;
        const double o01 = a01 * ip, o02 = a02 * ip, o12 = a12 * ip;
        double r = 0.5 * (b00 * (b11 * b22 - o12 * o12)
                        - o01 * (o01 * b22 - o12 * o02)
                        + o02 * (o01 * o12 - b11 * o02));
        r = fmin(1.0, fmax(-1.0, r));
        const double phi = acos(r) * (1.0 / 3.0);
        const double lam = m + 2.0 * p * cos(phi);   // largest eigenvalue

        // Eigenvector: best cross product of rows of C = A - lam I
        const double c00 = a00 - lam, c11 = a11 - lam, c22 = a22 - lam;
        // row0 = (c00, a01, a02), row1 = (a01, c11, a12), row2 = (a02, a12, c22)
        double v0, v1, v2, best = -1.0;
        {   // row0 x row1
            const double e0 = a01 * a12 - a02 * c11;
            const double e1 = a02 * a01 - c00 * a12;
            const double e2 = c00 * c11 - a01 * a01;
            const double n = e0 * e0 + e1 * e1 + e2 * e2;
            v0 = e0; v1 = e1; v2 = e2; best = n;
        }
        {   // row0 x row2
            const double e0 = a01 * c22 - a02 * a12;
            const double e1 = a02 * a02 - c00 * c22;
            const double e2 = c00 * a12 - a01 * a02;
            const double n = e0 * e0 + e1 * e1 + e2 * e2;
            if (n > best) { v0 = e0; v1 = e1; v2 = e2; best = n; }
        }
        {   // row1 x row2
            const double e0 = c11 * c22 - a12 * a12;
            const double e1 = a12 * a02 - a01 * c22;
            const double e2 = a01 * a12 - c11 * a02;
            const double n = e0 * e0 + e1 * e1 + e2 * e2;
            if (n > best) { v0 = e0; v1 = e1; v2 = e2; best = n; }
        }
        const double rn = 1.0 / sqrt(best);
        z0 = v0 * rn; z1 = v1 * rn; z2 = v2 * rn;
    }

    // Quaternion forward axis: rotate (0,0,1) by raw (unnormalized) Qrot,
    // replicating the reference formula exactly.
    const double qx = (double)x[3 * T_LEN];
    const double qy = (double)x[4 * T_LEN];
    const double qz = (double)x[5 * T_LEN];
    const double qw = (double)x[6 * T_LEN];
    const double zf0 = 2.0 * (qx * qz + qw * qy);
    const double zf1 = 2.0 * (qy * qz - qw * qx);
    const double zf2 = 1.0 - 2.0 * (qx * qx + qy * qy);

    if (zf0 * z0 + zf1 * z1 + zf2 * z2 < 0.0) {
        z0 = -z0; z1 = -z1; z2 = -z2;
    }

    const double u0 = (double)ref_axis[0], u1 = (double)ref_axis[1], u2 = (double)ref_axis[2];
    // new_right = cross(up, z)
    const double r0 = u1 * z2 - u2 * z1;
    const double r1 = u2 * z0 - u0 * z2;
    const double r2 = u0 * z1 - u1 * z0;
    // new_fwd = cross(right, up)
    const double f0 = r1 * u2 - r2 * u1;
    const double f1 = r2 * u0 - r0 * u2;
    const double f2 = r0 * u1 - r1 * u0;

    // refPos = Xpos[:, :, 0]
    const double p0 = (double)x[0];
    const double p1 = (double)x[T_LEN];
    const double p2r = (double)x[2 * T_LEN];

    const double B[3][3] = {{r0, r1, r2}, {u0, u1, u2}, {f0, f1, f2}};
#pragma unroll
    for (int i = 0; i < 3; i++) {
        g_params[3 * i + 0] = (float)B[i][0];
        g_params[3 * i + 1] = (float)B[i][1];
        g_params[3 * i + 2] = (float)B[i][2];
        g_params[9 + i] = (float)(B[i][0] * p0 + B[i][1] * p1 + B[i][2] * p2r);
    }
}

// ---------------------------------------------------------------------------
// Kernel 3: streaming transform + copy. All 6 loads batched up front for MLP.
// out rows 0..2 = B @ Xpos - o ; out rows 3..5 = x rows 7..9
// ---------------------------------------------------------------------------
__global__ __launch_bounds__(256) void k_transform(const float4* __restrict__ x,
                                                   float4* __restrict__ out) {
    const int i = blockIdx.x * blockDim.x + threadIdx.x;
    if (i >= T4) return;

    // Issue all 6 global loads before any dependent compute (MLP batching).
    const float4 a = x[i];            // Xpos rows: likely L2-resident after reduce
    const float4 b = x[T4 + i];
    const float4 c = x[2 * T4 + i];
    const float4 a0 = __ldcs(&x[7 * T4 + i]);   // Add rows: streamed
    const float4 a1 = __ldcs(&x[8 * T4 + i]);
    const float4 a2 = __ldcs(&x[9 * T4 + i]);

    const float b00 = g_params[0], b01 = g_params[1], b02 = g_params[2];
    const float b10 = g_params[3], b11 = g_params[4], b12 = g_params[5];
    const float b20 = g_params[6], b21 = g_params[7], b22 = g_params[8];
    const float o0 = g_params[9], o1 = g_params[10], o2 = g_params[11];

    float4 y0, y1, y2;
    y0.x = fmaf(b00, a.x, fmaf(b01, b.x, fmaf(b02, c.x, -o0)));
    y0.y = fmaf(b00, a.y, fmaf(b01, b.y, fmaf(b02, c.y, -o0)));
    y0.z = fmaf(b00, a.z, fmaf(b01, b.z, fmaf(b02, c.z, -o0)));
    y0.w = fmaf(b00, a.w, fmaf(b01, b.w, fmaf(b02, c.w, -o0)));

    y1.x = fmaf(b10, a.x, fmaf(b11, b.x, fmaf(b12, c.x, -o1)));
    y1.y = fmaf(b10, a.y, fmaf(b11, b.y, fmaf(b12, c.y, -o1)));
    y1.z = fmaf(b10, a.z, fmaf(b11, b.z, fmaf(b12, c.z, -o1)));
    y1.w = fmaf(b10, a.w, fmaf(b11, b.w, fmaf(b12, c.w, -o1)));

    y2.x = fmaf(b20, a.x, fmaf(b21, b.x, fmaf(b22, c.x, -o2)));
    y2.y = fmaf(b20, a.y, fmaf(b21, b.y, fmaf(b22, c.y, -o2)));
    y2.z = fmaf(b20, a.z, fmaf(b21, b.z, fmaf(b22, c.z, -o2)));
    y2.w = fmaf(b20, a.w, fmaf(b21, b.w, fmaf(b22, c.w, -o2)));

    // Streaming stores: output is never re-read.
    __stcs(&out[i], y0);
    __stcs(&out[T4 + i], y1);
    __stcs(&out[2 * T4 + i], y2);
    __stcs(&out[3 * T4 + i], a0);
    __stcs(&out[4 * T4 + i], a1);
    __stcs(&out[5 * T4 + i], a2);
}

// ---------------------------------------------------------------------------
extern "C" void kernel_launch(void* const* d_in, const int* in_sizes, int n_in,
                              void* d_out, int out_size) {
    const float* x = (const float*)d_in[0];
    const float* ref_axis = (const float*)d_in[1];
    float* out = (float*)d_out;

    k_reduce<<<NB_RED, 256>>>((const float4*)x);
    k_finalize<<<1, 288>>>(x, ref_axis);
    k_transform<<<(T4 + 255) / 256, 256>>>((const float4*)x, (float4*)out);
}